// round 17
// baseline (speedup 1.0000x reference)
#include <cuda_runtime.h>
#include <cuda_bf16.h>
#include <cuda_fp16.h>
#include <math.h>
#include <stdint.h>

#define SEQL 2048
#define DIMN 2048
#define NHEADS 16
#define HDIM 128
#define HIDDEN 8192
#define LTCN 256
#define RMS_EPS 1.1920929e-07f
#define EPSQ 1.5e-3f
#define FIXCAP (1 << 20)
typedef long long ll;

// ======================= scratch =======================
__align__(256) __device__ float g_qkv[2048LL * 6144];
__align__(256) __device__ float g_xn32[2048LL * 2048];
__align__(256) __device__ float g_wT[6144LL * 2048];
__align__(256) __device__ int   g_fixlist[FIXCAP];
__align__(256) __device__ int   g_fixcnt[1];
__align__(256) __device__ __half g_sc16[(ll)NHEADS * SEQL * SEQL];
__align__(256) __device__ float g_h[SEQL * DIMN];
__align__(256) __device__ float g_part[8LL * 2048 * 768];
__align__(256) __device__ float g_l0[SEQL * LTCN];
__align__(256) __device__ float g_l1[SEQL * LTCN];

// ======================= packed fp16 =======================
__align__(256) __device__ __half h_xn2[2048LL * 4096];    // [hi|lo] 2-term
__align__(256) __device__ __half h_qkvw[6144LL * 4096];   // [hi|hi] 2-term
__align__(256) __device__ __half h_q[16LL * 2048 * 128];
__align__(256) __device__ __half h_k[16LL * 2048 * 128];
__align__(256) __device__ __half h_pr[16LL * 2048 * 2048];
__align__(256) __device__ __half h_vt[16LL * 128 * 2048];
__align__(256) __device__ __half h_at[2048LL * 2048];
__align__(256) __device__ __half h_ow[2048LL * 2048];
__align__(256) __device__ __half h_xn[2048LL * 2048];
__align__(256) __device__ __half h_guw[16384LL * 2048];   // interleaved gate/up
__align__(256) __device__ __half h_dw[2048LL * 8192];
__align__(256) __device__ __half h_pw[8192LL * 256];
__align__(256) __device__ __half h_c0w[768LL * 8192];
__align__(256) __device__ __half h_c1w[768LL * 256];
__align__(256) __device__ __half h_in[2048LL * 8192];
__align__(256) __device__ __half h_l0[2048LL * 256];
__align__(256) __device__ __half h_l1[2048LL * 256];
__align__(256) __device__ __half h_en[2048LL * 8192];

// ======================= helpers =======================
__device__ __forceinline__ uint32_t smem_u32(const void* p) {
    uint32_t a;
    asm("{ .reg .u64 t; cvta.to.shared.u64 t, %1; cvt.u32.u64 %0, t; }" : "=r"(a) : "l"(p));
    return a;
}
__device__ __forceinline__ void cp16(uint32_t dst, const void* src) {
    asm volatile("cp.async.cg.shared.global [%0], [%1], 16;" :: "r"(dst), "l"(src));
}
#define CP_COMMIT()  asm volatile("cp.async.commit_group;" ::: "memory")
#define CP_WAIT1()   asm volatile("cp.async.wait_group 1;" ::: "memory")
#define CP_WAIT2()   asm volatile("cp.async.wait_group 2;" ::: "memory")

__device__ __forceinline__ void ldmx4(uint32_t* r, uint32_t addr) {
    asm volatile("ldmatrix.sync.aligned.m8n8.x4.shared.b16 {%0,%1,%2,%3}, [%4];"
                 : "=r"(r[0]), "=r"(r[1]), "=r"(r[2]), "=r"(r[3]) : "r"(addr));
}
__device__ __forceinline__ void mma_fp(float* d, const uint32_t* a, uint32_t b0, uint32_t b1) {
    asm volatile(
        "mma.sync.aligned.m16n8k16.row.col.f32.f16.f16.f32 "
        "{%0,%1,%2,%3}, {%4,%5,%6,%7}, {%8,%9}, {%0,%1,%2,%3};"
        : "+f"(d[0]), "+f"(d[1]), "+f"(d[2]), "+f"(d[3])
        : "r"(a[0]), "r"(a[1]), "r"(a[2]), "r"(a[3]), "r"(b0), "r"(b1));
}

#define PITCH 80

// ======================= HMMA GEMM 128x256, 3-stage (fp16) =======================
template <bool CAUSAL, bool OUT16, bool D16>
__global__ __launch_bounds__(256, 1) void hgemm256(
    const __half* __restrict__ A, int lda, ll sA,
    const __half* __restrict__ B, int ldb, ll sB,
    float* __restrict__ C, int ldc, ll sC,
    const float* __restrict__ Dadd, int ldd, ll sD,
    int Kp, float alpha)
{
    const int bm = blockIdx.y * 128;
    const int bn = blockIdx.x * 256;
    if (CAUSAL && bn > bm + 127) return;

    const int z = blockIdx.z;
    A += (ll)z * sA;
    B += (ll)z * sB;
    __half* Ch = nullptr;
    if (OUT16) Ch = (__half*)C + (ll)z * sC;
    else C += (ll)z * sC;
    const __half* Dh = nullptr;
    if (Dadd) {
        if (D16) Dh = (const __half*)Dadd + (ll)z * sD;
        else Dadd += (ll)z * sD;
    }

    extern __shared__ char smem[];
    const uint32_t sb = smem_u32(smem);
    const int tid = threadIdx.x;
    const int lane = tid & 31;
    const int wid = tid >> 5;
    const int wm = wid & 1;
    const int wn = wid >> 1;

    float acc[4][8][4];
#pragma unroll
    for (int i = 0; i < 4; i++)
#pragma unroll
        for (int j = 0; j < 8; j++)
#pragma unroll
            for (int t = 0; t < 4; t++) acc[i][j][t] = 0.f;

    const int nK = Kp >> 5;

    auto load_stage = [&](int s, int b) {
        const uint32_t Ad = sb + b * 30720;
        const char* Ag = (const char*)A + (ll)s * 64;
#pragma unroll
        for (int j = 0; j < 2; j++) {
            int q = tid + j * 256;
            int r = q >> 2, c = q & 3;
            cp16(Ad + r * PITCH + c * 16, Ag + (ll)(bm + r) * lda * 2 + c * 16);
        }
        const uint32_t Bd = Ad + 10240;
        const char* Bg = (const char*)B + (ll)s * 64;
#pragma unroll
        for (int j = 0; j < 4; j++) {
            int q = tid + j * 256;
            int r = q >> 2, c = q & 3;
            cp16(Bd + r * PITCH + c * 16, Bg + (ll)(bn + r) * ldb * 2 + c * 16);
        }
    };

    load_stage(0, 0); CP_COMMIT();
    if (nK > 1) load_stage(1, 1);
    CP_COMMIT();
    if (nK > 2) load_stage(2, 2);
    CP_COMMIT();

    int buf = 0;
    for (int i = 0; i < nK; i++) {
        CP_WAIT2();
        __syncthreads();
        const uint32_t Ab = sb + buf * 30720;
        const uint32_t Bb = Ab + 10240;
#pragma unroll
        for (int ks = 0; ks < 2; ks++) {
            uint32_t a[4][4];
#pragma unroll
            for (int mt = 0; mt < 4; mt++) {
                const int row = wm * 64 + mt * 16 + (lane & 15);
                ldmx4(a[mt], Ab + row * PITCH + (ks * 2 + (lane >> 4)) * 16);
            }
            uint32_t bf[4][4];
#pragma unroll
            for (int p = 0; p < 4; p++) {
                const int nrow = wn * 64 + p * 16 + ((lane >> 4) << 3) + (lane & 7);
                ldmx4(bf[p], Bb + nrow * PITCH + (ks * 2 + ((lane >> 3) & 1)) * 16);
            }
#pragma unroll
            for (int mt = 0; mt < 4; mt++)
#pragma unroll
                for (int j = 0; j < 8; j++)
                    mma_fp(acc[mt][j], a[mt], bf[j >> 1][(j & 1) * 2], bf[j >> 1][(j & 1) * 2 + 1]);
        }
        __syncthreads();
        if (i + 3 < nK) load_stage(i + 3, buf);
        CP_COMMIT();
        buf = (buf == 2) ? 0 : buf + 1;
    }

    const int r0 = lane >> 2;
    const int c0 = (lane & 3) * 2;
#pragma unroll
    for (int mt = 0; mt < 4; mt++) {
#pragma unroll
        for (int j = 0; j < 8; j++) {
            const int col = bn + wn * 64 + j * 8 + c0;
            const ll row0 = bm + wm * 64 + mt * 16 + r0;
            const ll row1 = row0 + 8;
            float2 v0 = {alpha * acc[mt][j][0], alpha * acc[mt][j][1]};
            float2 v1 = {alpha * acc[mt][j][2], alpha * acc[mt][j][3]};
            if (Dadd) {
                if (D16) {
                    float2 d0 = __half22float2(*reinterpret_cast<const __half2*>(Dh + row0 * ldd + col));
                    float2 d1 = __half22float2(*reinterpret_cast<const __half2*>(Dh + row1 * ldd + col));
                    v0.x += d0.x; v0.y += d0.y; v1.x += d1.x; v1.y += d1.y;
                } else {
                    float2 d0 = *reinterpret_cast<const float2*>(Dadd + row0 * ldd + col);
                    float2 d1 = *reinterpret_cast<const float2*>(Dadd + row1 * ldd + col);
                    v0.x += d0.x; v0.y += d0.y; v1.x += d1.x; v1.y += d1.y;
                }
            }
            if (OUT16) {
                *reinterpret_cast<__half2*>(Ch + row0 * ldc + col) = __floats2half2_rn(v0.x, v0.y);
                *reinterpret_cast<__half2*>(Ch + row1 * ldc + col) = __floats2half2_rn(v1.x, v1.y);
            } else {
                *reinterpret_cast<float2*>(C + row0 * ldc + col) = v0;
                *reinterpret_cast<float2*>(C + row1 * ldc + col) = v1;
            }
        }
    }
}

// ======================= gate/up fused GEMM (fp16, interleaved weights) ============
__global__ __launch_bounds__(256, 1) void hgemm_gu(
    const __half* __restrict__ A, const __half* __restrict__ B,
    __half* __restrict__ hin)
{
    const int bm = blockIdx.y * 128;
    const int bn = blockIdx.x * 256;
    extern __shared__ char smem[];
    const uint32_t sb = smem_u32(smem);
    const int tid = threadIdx.x;
    const int lane = tid & 31;
    const int wid = tid >> 5;
    const int wm = wid & 1;
    const int wn = wid >> 1;

    float acc[4][8][4];
#pragma unroll
    for (int i = 0; i < 4; i++)
#pragma unroll
        for (int j = 0; j < 8; j++)
#pragma unroll
            for (int t = 0; t < 4; t++) acc[i][j][t] = 0.f;

    const int nK = 2048 >> 5;

    auto load_stage = [&](int s, int b) {
        const uint32_t Ad = sb + b * 30720;
        const char* Ag = (const char*)A + (ll)s * 64;
#pragma unroll
        for (int j = 0; j < 2; j++) {
            int q = tid + j * 256;
            int r = q >> 2, c = q & 3;
            cp16(Ad + r * PITCH + c * 16, Ag + (ll)(bm + r) * 2048 * 2 + c * 16);
        }
        const uint32_t Bd = Ad + 10240;
        const char* Bg = (const char*)B + (ll)s * 64;
#pragma unroll
        for (int j = 0; j < 4; j++) {
            int q = tid + j * 256;
            int r = q >> 2, c = q & 3;
            cp16(Bd + r * PITCH + c * 16, Bg + (ll)(bn + r) * 2048 * 2 + c * 16);
        }
    };

    load_stage(0, 0); CP_COMMIT();
    load_stage(1, 1); CP_COMMIT();
    load_stage(2, 2); CP_COMMIT();

    int buf = 0;
    for (int i = 0; i < nK; i++) {
        CP_WAIT2();
        __syncthreads();
        const uint32_t Ab = sb + buf * 30720;
        const uint32_t Bb = Ab + 10240;
#pragma unroll
        for (int ks = 0; ks < 2; ks++) {
            uint32_t a[4][4];
#pragma unroll
            for (int mt = 0; mt < 4; mt++) {
                const int row = wm * 64 + mt * 16 + (lane & 15);
                ldmx4(a[mt], Ab + row * PITCH + (ks * 2 + (lane >> 4)) * 16);
            }
            uint32_t bf[4][4];
#pragma unroll
            for (int p = 0; p < 4; p++) {
                const int nrow = wn * 64 + p * 16 + ((lane >> 4) << 3) + (lane & 7);
                ldmx4(bf[p], Bb + nrow * PITCH + (ks * 2 + ((lane >> 3) & 1)) * 16);
            }
#pragma unroll
            for (int mt = 0; mt < 4; mt++)
#pragma unroll
                for (int j = 0; j < 8; j++)
                    mma_fp(acc[mt][j], a[mt], bf[j >> 1][(j & 1) * 2], bf[j >> 1][(j & 1) * 2 + 1]);
        }
        __syncthreads();
        if (i + 3 < nK) load_stage(i + 3, buf);
        CP_COMMIT();
        buf = (buf == 2) ? 0 : buf + 1;
    }

    const int r0 = lane >> 2;
    const int c0 = (lane & 3) * 2;
#pragma unroll
    for (int mt = 0; mt < 4; mt++) {
#pragma unroll
        for (int p = 0; p < 4; p++) {
            const int ob = ((bn + wn * 64) >> 1) + p * 8 + c0;
            const ll row0 = bm + wm * 64 + mt * 16 + r0;
            const ll row1 = row0 + 8;
            const float* ga = acc[mt][2 * p];
            const float* ua = acc[mt][2 * p + 1];
            float v0x = (ga[0] / (1.f + expf(-ga[0]))) * ua[0];
            float v0y = (ga[1] / (1.f + expf(-ga[1]))) * ua[1];
            float v1x = (ga[2] / (1.f + expf(-ga[2]))) * ua[2];
            float v1y = (ga[3] / (1.f + expf(-ga[3]))) * ua[3];
            *reinterpret_cast<__half2*>(hin + row0 * 8192 + ob) = __floats2half2_rn(v0x, v0y);
            *reinterpret_cast<__half2*>(hin + row1 * 8192 + ob) = __floats2half2_rn(v1x, v1y);
        }
    }
}

// ======================= HMMA GEMM 128x128, 2-stage (AV) =======================
template <bool CK, bool OUT16>
__global__ __launch_bounds__(256) void hgemm(
    const __half* __restrict__ A, int lda, ll sA,
    const __half* __restrict__ B, int ldb, ll sB,
    float* __restrict__ C, int ldc, ll sC,
    int Kp, float alpha)
{
    const int bm = blockIdx.y * 128;
    const int bn = blockIdx.x * 128;
    const int z = blockIdx.z;
    A += (ll)z * sA;
    B += (ll)z * sB;
    __half* Ch = nullptr;
    if (OUT16) Ch = (__half*)C + (ll)z * sC;
    else C += (ll)z * sC;

    __shared__ char smem[4 * 128 * PITCH];
    const uint32_t sb = smem_u32(smem);
    const uint32_t Abase[2] = {sb, sb + 128 * PITCH};
    const uint32_t Bbase[2] = {sb + 2 * 128 * PITCH, sb + 3 * 128 * PITCH};

    const int tid = threadIdx.x;
    const int lane = tid & 31;
    const int wid = tid >> 5;
    const int wm = wid & 3;
    const int wn = wid >> 2;

    float acc[2][8][4];
#pragma unroll
    for (int i = 0; i < 2; i++)
#pragma unroll
        for (int j = 0; j < 8; j++)
#pragma unroll
            for (int t = 0; t < 4; t++) acc[i][j][t] = 0.f;

    const int KpEff = CK ? (bm + 128 < Kp ? bm + 128 : Kp) : Kp;
    const int nK = KpEff >> 5;

    auto load_stage = [&](int s, int b) {
        const char* Ag = (const char*)A + (ll)s * 64;
#pragma unroll
        for (int j = 0; j < 2; j++) {
            int q = tid + j * 256;
            int r = q >> 2, c = q & 3;
            cp16(Abase[b] + r * PITCH + c * 16, Ag + (ll)(bm + r) * lda * 2 + c * 16);
        }
        const char* Bg = (const char*)B + (ll)s * 64;
#pragma unroll
        for (int j = 0; j < 2; j++) {
            int q = tid + j * 256;
            int r = q >> 2, c = q & 3;
            cp16(Bbase[b] + r * PITCH + c * 16, Bg + (ll)(bn + r) * ldb * 2 + c * 16);
        }
    };

    load_stage(0, 0); CP_COMMIT();
    if (nK > 1) load_stage(1, 1);
    CP_COMMIT();

    for (int i = 0; i < nK; i++) {
        const int buf = i & 1;
        CP_WAIT1();
        __syncthreads();
        const uint32_t Ab = Abase[buf], Bb = Bbase[buf];
#pragma unroll
        for (int ks = 0; ks < 2; ks++) {
            uint32_t a[2][4];
#pragma unroll
            for (int mt = 0; mt < 2; mt++) {
                const int row = wm * 32 + mt * 16 + (lane & 15);
                ldmx4(a[mt], Ab + row * PITCH + (ks * 2 + (lane >> 4)) * 16);
            }
            uint32_t bf[4][4];
#pragma unroll
            for (int p = 0; p < 4; p++) {
                const int nrow = wn * 64 + p * 16 + ((lane >> 4) << 3) + (lane & 7);
                ldmx4(bf[p], Bb + nrow * PITCH + (ks * 2 + ((lane >> 3) & 1)) * 16);
            }
#pragma unroll
            for (int mt = 0; mt < 2; mt++)
#pragma unroll
                for (int j = 0; j < 8; j++)
                    mma_fp(acc[mt][j], a[mt], bf[j >> 1][(j & 1) * 2], bf[j >> 1][(j & 1) * 2 + 1]);
        }
        __syncthreads();
        if (i + 2 < nK) load_stage(i + 2, buf);
        CP_COMMIT();
    }

    const int r0 = lane >> 2;
    const int c0 = (lane & 3) * 2;
#pragma unroll
    for (int mt = 0; mt < 2; mt++) {
#pragma unroll
        for (int j = 0; j < 8; j++) {
            const int col = bn + wn * 64 + j * 8 + c0;
            const ll row0 = bm + wm * 32 + mt * 16 + r0;
            const ll row1 = row0 + 8;
            float2 v0 = {alpha * acc[mt][j][0], alpha * acc[mt][j][1]};
            float2 v1 = {alpha * acc[mt][j][2], alpha * acc[mt][j][3]};
            if (OUT16) {
                *reinterpret_cast<__half2*>(Ch + row0 * ldc + col) = __floats2half2_rn(v0.x, v0.y);
                *reinterpret_cast<__half2*>(Ch + row1 * ldc + col) = __floats2half2_rn(v1.x, v1.y);
            } else {
                *reinterpret_cast<float2*>(C + row0 * ldc + col) = v0;
                *reinterpret_cast<float2*>(C + row1 * ldc + col) = v1;
            }
        }
    }
}

// ======================= pack helpers =======================
// transpose to fp16 1-term with z batching
__global__ void splitT_h16_k(
    const float* __restrict__ in, int ldin, ll inZcols,
    __half* __restrict__ out, ll outZ, int K)
{
    __shared__ float t[32][33];
    const int k0 = blockIdx.x * 32, n0 = blockIdx.y * 32;
    const int tx = threadIdx.x, ty = threadIdx.y;
    const float* ip = in + (ll)blockIdx.z * inZcols;
#pragma unroll
    for (int j = 0; j < 4; j++)
        t[ty + j * 8][tx] = ip[(ll)(k0 + ty + j * 8) * ldin + n0 + tx];
    __syncthreads();
    __half* op = out + (ll)blockIdx.z * outZ;
#pragma unroll
    for (int j = 0; j < 4; j++) {
        const int n = n0 + ty + j * 8, k = k0 + tx;
        op[(ll)n * K + k] = __float2half_rn(t[tx][ty + j * 8]);
    }
}

// transpose to fp16 2-term [hi|hi] + fp32 transposed copy (QKV weights)
__global__ void splitT_h16dup_f32_k(
    const float* __restrict__ in, int ldin,
    __half* __restrict__ out, int K, float* __restrict__ outf)
{
    __shared__ float t[32][33];
    const int k0 = blockIdx.x * 32, n0 = blockIdx.y * 32;
    const int tx = threadIdx.x, ty = threadIdx.y;
#pragma unroll
    for (int j = 0; j < 4; j++)
        t[ty + j * 8][tx] = in[(ll)(k0 + ty + j * 8) * ldin + n0 + tx];
    __syncthreads();
#pragma unroll
    for (int j = 0; j < 4; j++) {
        const int n = n0 + ty + j * 8, k = k0 + tx;
        const float v = t[tx][ty + j * 8];
        const __half hv = __float2half_rn(v);
        __half* base = out + (ll)n * (2 * K) + k;
        base[0] = hv;
        base[K] = hv;
        outf[(ll)n * K + k] = v;
    }
}

// interleaved gate/up fp16 transpose pack
__global__ void splitT_gu_k(
    const float* __restrict__ gatew, const float* __restrict__ upw,
    __half* __restrict__ out)
{
    __shared__ float t[32][33];
    const int k0 = blockIdx.x * 32, n0 = blockIdx.y * 32;
    const int tx = threadIdx.x, ty = threadIdx.y;
    const int base = n0 >> 1;
    const float* src = (tx < 16) ? gatew : upw;
    const int scol = base + (tx & 15);
#pragma unroll
    for (int j = 0; j < 4; j++)
        t[ty + j * 8][tx] = src[(ll)(k0 + ty + j * 8) * 8192 + scol];
    __syncthreads();
#pragma unroll
    for (int j = 0; j < 4; j++) {
        const int nl = ty + j * 8;
        const int grp = nl >> 4, w16 = nl & 15;
        const int half = w16 >> 3, col = grp * 8 + (w16 & 7);
        const int s = half * 16 + col;
        out[(ll)(n0 + nl) * 2048 + k0 + tx] = __float2half_rn(t[tx][s]);
    }
}

// ======================= spike-threshold fixup =======================
__global__ void zero_cnt_k(int* cnt) { if (threadIdx.x == 0) cnt[0] = 0; }

__global__ __launch_bounds__(256) void flag_k(
    const float* __restrict__ qkv, int* __restrict__ cnt, int* __restrict__ list)
{
    const ll i = ((ll)blockIdx.x * 256 + threadIdx.x) * 4;
    const float4 v = *reinterpret_cast<const float4*>(qkv + i);
#pragma unroll
    for (int j = 0; j < 4; j++) {
        const float val = (&v.x)[j];
        if (fabsf(val - 1.0f) < EPSQ) {
            int p = atomicAdd(cnt, 1);
            if (p < FIXCAP) list[p] = (int)(i + j);
        }
    }
}

// one warp per flagged entry: exact fp32 dot of xn row x wT row
__global__ __launch_bounds__(256) void fix_k(
    float* __restrict__ qkv, const float* __restrict__ xn, const float* __restrict__ wT,
    const int* __restrict__ cnt, const int* __restrict__ list)
{
    const int warp = (blockIdx.x * 256 + threadIdx.x) >> 5;
    const int lane = threadIdx.x & 31;
    const int nwarps = gridDim.x * 8;
    int n = cnt[0];
    if (n > FIXCAP) n = FIXCAP;
    for (int e = warp; e < n; e += nwarps) {
        const int idx = list[e];
        const int r = idx / 6144, c = idx % 6144;
        const float* xr = xn + (ll)r * 2048;
        const float* wr = wT + (ll)c * 2048;
        float s = 0.f;
        for (int k = lane; k < 2048; k += 32) s = fmaf(xr[k], wr[k], s);
#pragma unroll
        for (int o = 16; o > 0; o >>= 1) s += __shfl_xor_sync(0xFFFFFFFFu, s, o);
        if (lane == 0) qkv[idx] = s;
    }
}

// ======================= fused elementwise kernels =======================
// rmsnorm -> fp16 2-term [hi|lo] pack + fp32 copy
__global__ __launch_bounds__(256) void rmsnorm_h16x2_k(
    const float* __restrict__ x, const float* __restrict__ w,
    __half* __restrict__ out, float* __restrict__ out32)
{
    const int r = blockIdx.x, tid = threadIdx.x;
    const float* xr = x + (ll)r * DIMN;
    float ss = 0.f;
    for (int i = tid; i < DIMN; i += 256) { float v = xr[i]; ss += v * v; }
    __shared__ float red[256];
    red[tid] = ss; __syncthreads();
    for (int s = 128; s > 0; s >>= 1) { if (tid < s) red[tid] += red[tid + s]; __syncthreads(); }
    const float scale = rsqrtf(red[0] * (1.0f / DIMN) + RMS_EPS);
    __half* orow = out + (ll)r * 4096;
    float* frow = out32 + (ll)r * 2048;
    for (int i = tid; i < DIMN; i += 256) {
        const float v = xr[i] * scale * w[i];
        const __half hv = __float2half_rn(v);
        const __half lv = __float2half_rn(v - __half2float(hv));
        orow[i] = hv;
        orow[2048 + i] = lv;
        frow[i] = v;
    }
}

__global__ __launch_bounds__(256) void rmsnorm_h16_k(
    const float* __restrict__ x, const float* __restrict__ w, __half* __restrict__ out)
{
    const int r = blockIdx.x, tid = threadIdx.x;
    const float* xr = x + (ll)r * DIMN;
    float ss = 0.f;
    for (int i = tid; i < DIMN; i += 256) { float v = xr[i]; ss += v * v; }
    __shared__ float red[256];
    red[tid] = ss; __syncthreads();
    for (int s = 128; s > 0; s >>= 1) { if (tid < s) red[tid] += red[tid + s]; __syncthreads(); }
    const float scale = rsqrtf(red[0] * (1.0f / DIMN) + RMS_EPS);
    __half* orow = out + (ll)r * DIMN;
    for (int i = tid; i < DIMN; i += 256)
        orow[i] = __float2half_rn(xr[i] * scale * w[i]);
}

__global__ __launch_bounds__(256) void spike_rope_h16_k(
    const float* __restrict__ q, int stride, __half* __restrict__ out)
{
    const int idx = blockIdx.x * 256 + threadIdx.x;
    const int d = idx & 63;
    const int h = (idx >> 6) & (NHEADS - 1);
    const int s = idx >> 10;
    const ll base = (ll)s * stride + h * HDIM;
    const float a = q[base + d];
    const float b = q[base + d + 64];
    const float sa = a > 1.0f ? 1.f : 0.f;
    const float sb = b > 1.0f ? 1.f : 0.f;
    const float invf = powf(10000.0f, -(float)d * (1.0f / 64.0f));
    const float fr = (float)s * invf;
    double sd, cd;
    sincos((double)fr, &sd, &cd);
    const float c = (float)cd, si = (float)sd;
    __half* op = out + (ll)h * (SEQL * HDIM) + (ll)s * HDIM;
    op[d]      = __float2half_rn(sa * c - sb * si);
    op[d + 64] = __float2half_rn(sb * c + sa * si);
}

__global__ __launch_bounds__(256) void spike_k(float* __restrict__ q, int stride)
{
    const int idx = blockIdx.x * 256 + threadIdx.x;
    const int d = idx & 127;
    const int h = (idx >> 7) & (NHEADS - 1);
    const int s = idx >> 11;
    const ll base = (ll)s * stride + h * HDIM;
    q[base + d] = q[base + d] > 1.0f ? 1.f : 0.f;
}

// causal softmax: fp16 in/out; single pass with register-cached exp
__global__ __launch_bounds__(256) void softmax_h16_k(
    const __half* __restrict__ sc, __half* __restrict__ pr)
{
    const int q = blockIdx.x, h = blockIdx.y, tid = threadIdx.x;
    const __half* row = sc + ((ll)h * SEQL + q) * SEQL;
    __half* orow = pr + ((ll)h * SEQL + q) * SEQL;
    const int n = q + 1;
    __shared__ float red[256];
    float ev[8];
    float sum = 0.f;
    int j = 0;
    for (int i = tid; i < n; i += 256, j++) {
        ev[j] = expf(__half2float(row[i]));
        sum += ev[j];
    }
    red[tid] = sum; __syncthreads();
    for (int s = 128; s > 0; s >>= 1) { if (tid < s) red[tid] += red[tid + s]; __syncthreads(); }
    const float inv = 1.0f / red[0];
    j = 0;
    for (int i = tid; i < n; i += 256, j++)
        orow[i] = __float2half_rn(ev[j] * inv);
    const int nz = (n + 127) & ~127;
    const __half z = __float2half_rn(0.f);
    for (int i = n + tid; i < nz; i += 256) orow[i] = z;
}

// LTC combine + fused fp16 pack
__global__ __launch_bounds__(256) void ltc_combine_k(
    const float* __restrict__ t, int nz, ll zstride,
    const float* __restrict__ tb, const float* __restrict__ gb,
    const float* __restrict__ ib, const float* __restrict__ hb,
    float* __restrict__ out, __half* __restrict__ h16)
{
    const int i = blockIdx.x * 256 + threadIdx.x;
    const int r = i >> 8;
    const int n = i & (LTCN - 1);
    float tv = 0.f, gv = 0.f, iv = 0.f;
    for (int z = 0; z < nz; z++) {
        const float* base = t + (ll)z * zstride + (ll)r * 768;
        tv += base[n]; gv += base[256 + n]; iv += base[512 + n];
    }
    const float tau = 0.1f + 9.9f / (1.f + expf(-(tv + tb[n])));
    const float gt  = 1.f / (1.f + expf(-(gv + gb[n])));
    const float ic  = tanhf(iv + ib[n]);
    const float hc  = tanhf(hb[n]);
    const float target = gt * ic + (1.f - gt) * hc;
    const float o = tanhf(target / (tau + 1e-8f));
    out[i] = o;
    if (h16) h16[i] = __float2half_rn(o);
}

// ======================= launcher =======================
static inline float* SYMF(const void* s) { void* p; cudaGetSymbolAddress(&p, s); return (float*)p; }
static inline __half* SYMH(const void* s) { void* p; cudaGetSymbolAddress(&p, s); return (__half*)p; }
static inline int* SYMI(const void* s) { void* p; cudaGetSymbolAddress(&p, s); return (int*)p; }

extern "C" void kernel_launch(void* const* d_in, const int* in_sizes, int n_in,
                              void* d_out, int out_size)
{
    (void)in_sizes; (void)n_in; (void)out_size;
    const float* x     = (const float*)d_in[0];
    const float* anw   = (const float*)d_in[1];
    const float* fnw   = (const float*)d_in[2];
    const float* qw    = (const float*)d_in[3];
    const float* kw    = (const float*)d_in[4];
    const float* vw    = (const float*)d_in[5];
    const float* ow    = (const float*)d_in[6];
    const float* gatew = (const float*)d_in[7];
    const float* upw   = (const float*)d_in[8];
    const float* downw = (const float*)d_in[9];
    const float* projw = (const float*)d_in[10];
    const float* c0tw  = (const float*)d_in[11];
    const float* c0tb  = (const float*)d_in[12];
    const float* c0gw  = (const float*)d_in[13];
    const float* c0gb  = (const float*)d_in[14];
    const float* c0iw  = (const float*)d_in[15];
    const float* c0ib  = (const float*)d_in[16];
    const float* c0hb  = (const float*)d_in[18];
    const float* c1tw  = (const float*)d_in[19];
    const float* c1tb  = (const float*)d_in[20];
    const float* c1gw  = (const float*)d_in[21];
    const float* c1gb  = (const float*)d_in[22];
    const float* c1iw  = (const float*)d_in[23];
    const float* c1ib  = (const float*)d_in[24];
    const float* c1hb  = (const float*)d_in[26];
    float* out = (float*)d_out;

    float* qkv   = SYMF(g_qkv);
    float* xn32  = SYMF(g_xn32);
    float* wT    = SYMF(g_wT);
    int*   fcnt  = SYMI(g_fixcnt);
    int*   flist = SYMI(g_fixlist);
    __half* Hsc  = SYMH(g_sc16);
    float* h     = SYMF(g_h);
    float* part  = SYMF(g_part);
    float* l0    = SYMF(g_l0);    float* l1    = SYMF(g_l1);

    __half* Hxn2 = SYMH(h_xn2);  __half* Hqkw = SYMH(h_qkvw);
    __half* Hq   = SYMH(h_q);    __half* Hk   = SYMH(h_k);
    __half* Hpr  = SYMH(h_pr);   __half* Hvt  = SYMH(h_vt);
    __half* Hat  = SYMH(h_at);   __half* How  = SYMH(h_ow);
    __half* Hxn  = SYMH(h_xn);   __half* Hguw = SYMH(h_guw);
    __half* Hdw  = SYMH(h_dw);   __half* Hpw  = SYMH(h_pw);
    __half* Hc0w = SYMH(h_c0w);  __half* Hc1w = SYMH(h_c1w);
    __half* Hin  = SYMH(h_in);   __half* Hl0  = SYMH(h_l0);
    __half* Hl1  = SYMH(h_l1);   __half* Hen  = SYMH(h_en);

    const int SMEM3 = 3 * 30720;
    cudaFuncSetAttribute((const void*)hgemm256<false, false, false>, cudaFuncAttributeMaxDynamicSharedMemorySize, SMEM3);
    cudaFuncSetAttribute((const void*)hgemm256<true, true, false>,   cudaFuncAttributeMaxDynamicSharedMemorySize, SMEM3);
    cudaFuncSetAttribute((const void*)hgemm256<false, true, true>,   cudaFuncAttributeMaxDynamicSharedMemorySize, SMEM3);
    cudaFuncSetAttribute((const void*)hgemm_gu,                      cudaFuncAttributeMaxDynamicSharedMemorySize, SMEM3);

    const dim3 t32x8(32, 8);
    const float att_scale = 0.08838834764831845f;

    // ---- pack weights ----
    zero_cnt_k<<<1, 32>>>(fcnt);
    splitT_h16dup_f32_k<<<dim3(64, 64), t32x8>>>(qw, 2048, Hqkw, 2048, wT);
    splitT_h16dup_f32_k<<<dim3(64, 64), t32x8>>>(kw, 2048, Hqkw + 2048LL * 4096, 2048, wT + 2048LL * 2048);
    splitT_h16dup_f32_k<<<dim3(64, 64), t32x8>>>(vw, 2048, Hqkw + 4096LL * 4096, 2048, wT + 4096LL * 2048);
    splitT_h16_k<<<dim3(8, 8), t32x8>>>(c1tw, 256, 0, Hc1w, 0, 256);
    splitT_h16_k<<<dim3(8, 8), t32x8>>>(c1gw, 256, 0, Hc1w + 256LL * 256, 0, 256);
    splitT_h16_k<<<dim3(8, 8), t32x8>>>(c1iw, 256, 0, Hc1w + 512LL * 256, 0, 256);
    splitT_h16_k<<<dim3(64, 64), t32x8>>>(ow, 2048, 0, How, 0, 2048);
    splitT_gu_k<<<dim3(64, 512), t32x8>>>(gatew, upw, Hguw);
    splitT_h16_k<<<dim3(256, 64), t32x8>>>(downw, 2048, 0, Hdw, 0, 8192);
    splitT_h16_k<<<dim3(8, 256), t32x8>>>(projw, 8192, 0, Hpw, 0, 256);
    splitT_h16_k<<<dim3(256, 8), t32x8>>>(c0tw, 256, 0, Hc0w, 0, 8192);
    splitT_h16_k<<<dim3(256, 8), t32x8>>>(c0gw, 256, 0, Hc0w + 256LL * 8192, 0, 8192);
    splitT_h16_k<<<dim3(256, 8), t32x8>>>(c0iw, 256, 0, Hc0w + 512LL * 8192, 0, 8192);

    // ---- attention ----
    rmsnorm_h16x2_k<<<SEQL, 256>>>(x, anw, Hxn2, xn32);
    // QKV: fp16 2-term cross split, K'=4096
    hgemm256<false, false, false><<<dim3(24, 16), 256, SMEM3>>>(
        Hxn2, 4096, 0, Hqkw, 4096, 0, qkv, 6144, 0, nullptr, 0, 0, 4096, 1.f);
    // spike-threshold fixup: exact fp32 recompute for entries near 1.0
    flag_k<<<2048 * 6144 / 1024, 256>>>(qkv, fcnt, flist);
    fix_k<<<256, 256>>>(qkv, xn32, wT, fcnt, flist);
    spike_rope_h16_k<<<SEQL * NHEADS * 64 / 256, 256>>>(qkv, 6144, Hq);
    spike_rope_h16_k<<<SEQL * NHEADS * 64 / 256, 256>>>(qkv + 2048, 6144, Hk);
    spike_k<<<SEQL * NHEADS * 128 / 256, 256>>>(qkv + 4096, 6144);
    splitT_h16_k<<<dim3(64, 4, 16), t32x8>>>(qkv + 4096, 6144, 128, Hvt, 128LL * 2048, 2048);
    // scores: fp16 in/out, causal tile skip
    hgemm256<true, true, false><<<dim3(8, 16, 16), 256, SMEM3>>>(
        Hq, 128, 2048LL * 128, Hk, 128, 2048LL * 128,
        (float*)Hsc, 2048, (ll)SEQL * SEQL, nullptr, 0, 0, 128, att_scale);
    softmax_h16_k<<<dim3(SEQL, NHEADS), 256>>>(Hsc, Hpr);
    // AV: fp16, causal K-truncation, fp16 output
    hgemm<true, true><<<dim3(1, 16, 16), 256>>>(
        Hpr, 2048, 2048LL * 2048, Hvt, 2048, 128LL * 2048,
        (float*)Hat, 2048, 128, 2048, 1.f);
    // O projection: fp16 + fp32 residual
    hgemm256<false, false, false><<<dim3(8, 16), 256, SMEM3>>>(
        Hat, 2048, 0, How, 2048, 0, h, 2048, 0, x, 2048, 0, 2048, 1.f);

    // ---- LTC feed-forward ----
    rmsnorm_h16_k<<<SEQL, 256>>>(h, fnw, Hxn);
    hgemm_gu<<<dim3(64, 16), 256, SMEM3>>>(Hxn, Hguw, Hin);
    // cell 0: split-K x8
    hgemm256<false, false, false><<<dim3(3, 16, 8), 256, SMEM3>>>(
        Hin, 8192, 1024, Hc0w, 8192, 1024,
        part, 768, 2048LL * 768, nullptr, 0, 0, 1024, 1.f);
    ltc_combine_k<<<2048, 256>>>(part, 8, 2048LL * 768, c0tb, c0gb, c0ib, c0hb, l0, Hl0);
    // cell 1 (fp16 1-term)
    hgemm256<false, false, false><<<dim3(3, 16), 256, SMEM3>>>(
        Hl0, 256, 0, Hc1w, 256, 0, part, 768, 0, nullptr, 0, 0, 256, 1.f);
    ltc_combine_k<<<2048, 256>>>(part, 1, 0, c1tb, c1gb, c1ib, c1hb, l1, Hl1);
    // enhanced = inter(fp16) + l1 @ proj -> fp16
    hgemm256<false, true, true><<<dim3(32, 16), 256, SMEM3>>>(
        Hl1, 256, 0, Hpw, 256, 0,
        (float*)Hen, 8192, 0, (const float*)Hin, 8192, 0, 256, 1.f);
    // out = h + enhanced @ down_w
    hgemm256<false, false, false><<<dim3(8, 16), 256, SMEM3>>>(
        Hen, 8192, 0, Hdw, 8192, 0, out, 2048, 0, h, 2048, 0, 8192, 1.f);
}